// round 1
// baseline (speedup 1.0000x reference)
#include <cuda_runtime.h>

// Problem constants (fixed by the reference)
#define N_SAMPLES 4096
#define D_IN      1024
#define B_MID     512
#define E_TASKS   16
#define L1_LAMBDA 1e-4f

// GEMM tiling
#define BM 128
#define BN 128
#define BK 16
#define TM 8
#define TN 8
#define NTHREADS 256

// Static device scratch (no allocations allowed)
__device__ float g_h[(size_t)N_SAMPLES * B_MID];   // relu(h) staging, 8 MB
__device__ int   g_perm[N_SAMPLES];                // sample indices grouped by expert
__device__ int   g_counts[E_TASKS];
__device__ int   g_offsets[E_TASKS];
__device__ float g_l1pe[E_TASKS];

// ---------------------------------------------------------------------------
// Kernel 1: group samples by expert (single block). Deterministic results:
// intra-group order is atomics-dependent but every sample's output is
// independent of its position within its group.
// ---------------------------------------------------------------------------
__global__ void sort_kernel(const int* __restrict__ keys) {
    __shared__ int cnt[E_TASKS];
    __shared__ int off[E_TASKS];
    __shared__ int cur[E_TASKS];
    int tid = threadIdx.x;
    if (tid < E_TASKS) { cnt[tid] = 0; cur[tid] = 0; }
    __syncthreads();
    for (int n = tid; n < N_SAMPLES; n += blockDim.x)
        atomicAdd(&cnt[keys[n]], 1);
    __syncthreads();
    if (tid == 0) {
        int s = 0;
        for (int e = 0; e < E_TASKS; e++) { off[e] = s; s += cnt[e]; }
    }
    __syncthreads();
    if (tid < E_TASKS) { g_counts[tid] = cnt[tid]; g_offsets[tid] = off[tid]; }
    for (int n = tid; n < N_SAMPLES; n += blockDim.x) {
        int e = keys[n];
        int p = atomicAdd(&cur[e], 1);
        g_perm[off[e] + p] = n;
    }
}

// ---------------------------------------------------------------------------
// Kernel 2: per-expert gathered SGEMM  h = relu(Xg @ W1[e]^T + b1[e])
// NT gemm: X is [n][d] (K-major), W1[e] is [b][d] (K-major).
// Tile 128x128x16, 256 threads, 8x8 micro-tiles, smem layouts [k][m] / [k][b]
// for conflict-free float4 fragment loads.
// ---------------------------------------------------------------------------
__global__ __launch_bounds__(NTHREADS)
void gemm1_kernel(const float* __restrict__ x,
                  const float* __restrict__ W1,
                  const float* __restrict__ b1)
{
    const int e   = blockIdx.z;
    const int cnt = g_counts[e];
    const int m0  = blockIdx.y * BM;
    if (m0 >= cnt) return;
    const int off = g_offsets[e];
    const int n0  = blockIdx.x * BN;

    __shared__ __align__(16) float As[BK][BM];  // [k][m]
    __shared__ __align__(16) float Ws[BK][BN];  // [k][b]
    __shared__ int rows[BM];

    const int tid = threadIdx.x;
    const int tx  = tid & 15;    // 0..15 -> b groups
    const int ty  = tid >> 4;    // 0..15 -> m groups

    if (tid < BM) {
        int m = m0 + tid;
        rows[tid] = (m < cnt) ? g_perm[off + m] : -1;
    }
    __syncthreads();

    float acc[TM][TN];
#pragma unroll
    for (int i = 0; i < TM; i++)
#pragma unroll
        for (int j = 0; j < TN; j++) acc[i][j] = 0.f;

    const float* W1e = W1 + ((size_t)e * B_MID + n0) * D_IN;

    for (int k0 = 0; k0 < D_IN; k0 += BK) {
        // Load A tile: 128 rows x 16 k = 512 float4, 2 per thread.
        // f -> (m = f/4, c = f%4): 4 consecutive lanes read 64B of one row.
#pragma unroll
        for (int t = 0; t < 2; t++) {
            int f = tid + t * NTHREADS;
            int m = f >> 2;
            int c = f & 3;
            int r = rows[m];
            float4 v = make_float4(0.f, 0.f, 0.f, 0.f);
            if (r >= 0) v = *(const float4*)(x + (size_t)r * D_IN + k0 + 4 * c);
            As[4 * c + 0][m] = v.x;
            As[4 * c + 1][m] = v.y;
            As[4 * c + 2][m] = v.z;
            As[4 * c + 3][m] = v.w;
        }
        // Load W tile (same shape/mapping, rows are contiguous b-rows of W1[e])
#pragma unroll
        for (int t = 0; t < 2; t++) {
            int f = tid + t * NTHREADS;
            int b = f >> 2;
            int c = f & 3;
            float4 v = *(const float4*)(W1e + (size_t)b * D_IN + k0 + 4 * c);
            Ws[4 * c + 0][b] = v.x;
            Ws[4 * c + 1][b] = v.y;
            Ws[4 * c + 2][b] = v.z;
            Ws[4 * c + 3][b] = v.w;
        }
        __syncthreads();

#pragma unroll
        for (int kk = 0; kk < BK; kk++) {
            float a[TM], w[TN];
            // conflict-free: consecutive 16B chunks along the row
            *(float4*)&a[0] = *(const float4*)&As[kk][ty * TM + 0];
            *(float4*)&a[4] = *(const float4*)&As[kk][ty * TM + 4];
            *(float4*)&w[0] = *(const float4*)&Ws[kk][tx * TN + 0];
            *(float4*)&w[4] = *(const float4*)&Ws[kk][tx * TN + 4];
#pragma unroll
            for (int i = 0; i < TM; i++)
#pragma unroll
                for (int j = 0; j < TN; j++)
                    acc[i][j] = fmaf(a[i], w[j], acc[i][j]);
        }
        __syncthreads();
    }

    // Epilogue: h = relu(acc + b1[e][b]) -> g_h[row][b]
    float bb[TN];
#pragma unroll
    for (int j = 0; j < TN; j++)
        bb[j] = b1[e * B_MID + n0 + tx * TN + j];

#pragma unroll
    for (int i = 0; i < TM; i++) {
        int mi = ty * TM + i;
        if (m0 + mi < cnt) {
            int r = rows[mi];
            float* hp = g_h + (size_t)r * B_MID + n0 + tx * TN;
            float4 v0, v1;
            v0.x = fmaxf(acc[i][0] + bb[0], 0.f);
            v0.y = fmaxf(acc[i][1] + bb[1], 0.f);
            v0.z = fmaxf(acc[i][2] + bb[2], 0.f);
            v0.w = fmaxf(acc[i][3] + bb[3], 0.f);
            v1.x = fmaxf(acc[i][4] + bb[4], 0.f);
            v1.y = fmaxf(acc[i][5] + bb[5], 0.f);
            v1.z = fmaxf(acc[i][6] + bb[6], 0.f);
            v1.w = fmaxf(acc[i][7] + bb[7], 0.f);
            *(float4*)(hp + 0) = v0;
            *(float4*)(hp + 4) = v1;
        }
    }
}

// ---------------------------------------------------------------------------
// Kernel 3: layer 2 — one warp per sample. out[n] = h[n] . W2[e] + b2[e]
// ---------------------------------------------------------------------------
__global__ void layer2_kernel(const int* __restrict__ keys,
                              const float* __restrict__ W2,
                              const float* __restrict__ b2,
                              float* __restrict__ out)
{
    int gwarp = (blockIdx.x * blockDim.x + threadIdx.x) >> 5;
    int lane  = threadIdx.x & 31;
    if (gwarp >= N_SAMPLES) return;
    int e = keys[gwarp];
    const float* h = g_h + (size_t)gwarp * B_MID;
    const float* w = W2 + (size_t)e * B_MID;
    float s = 0.f;
#pragma unroll
    for (int b = lane; b < B_MID; b += 32)
        s = fmaf(h[b], w[b], s);
#pragma unroll
    for (int o = 16; o > 0; o >>= 1)
        s += __shfl_xor_sync(0xffffffffu, s, o);
    if (lane == 0) out[gwarp] = s + b2[e];
}

// ---------------------------------------------------------------------------
// Kernel 4: per-expert L1 (deterministic fixed-order block reduction)
// ---------------------------------------------------------------------------
__global__ void l1_kernel(const float* __restrict__ W1,
                          const float* __restrict__ b1,
                          const float* __restrict__ W2,
                          const float* __restrict__ b2)
{
    int e   = blockIdx.x;
    int tid = threadIdx.x;  // 256 threads
    float s = 0.f;
    const float* w1 = W1 + (size_t)e * B_MID * D_IN;
    for (int i = tid; i < B_MID * D_IN; i += 256) s += fabsf(w1[i]);
    const float* bb1 = b1 + e * B_MID;
    for (int i = tid; i < B_MID; i += 256) s += fabsf(bb1[i]);
    const float* w2 = W2 + e * B_MID;
    for (int i = tid; i < B_MID; i += 256) s += fabsf(w2[i]);
    if (tid == 0) s += fabsf(b2[e]);

    __shared__ float red[256];
    red[tid] = s;
    __syncthreads();
    for (int st = 128; st > 0; st >>= 1) {
        if (tid < st) red[tid] += red[tid + st];
        __syncthreads();
    }
    if (tid == 0) g_l1pe[e] = red[0];
}

// ---------------------------------------------------------------------------
// Kernel 5: final L1 scalar -> out[N] (only if the output buffer carries it)
// ---------------------------------------------------------------------------
__global__ void final_kernel(float* __restrict__ out, int out_size) {
    if (threadIdx.x == 0 && blockIdx.x == 0 && out_size > N_SAMPLES) {
        float s = 0.f;
        for (int e = 0; e < E_TASKS; e++)
            s += (float)g_counts[e] * g_l1pe[e];
        out[N_SAMPLES] = L1_LAMBDA * s;
    }
}

// ---------------------------------------------------------------------------
extern "C" void kernel_launch(void* const* d_in, const int* in_sizes, int n_in,
                              void* d_out, int out_size)
{
    const float* x    = (const float*)d_in[0];
    const int*   keys = (const int*)  d_in[1];
    const float* W1   = (const float*)d_in[2];
    const float* b1   = (const float*)d_in[3];
    const float* W2   = (const float*)d_in[4];
    const float* b2   = (const float*)d_in[5];
    float* out = (float*)d_out;

    sort_kernel<<<1, 256>>>(keys);

    dim3 grid(B_MID / BN, (N_SAMPLES + BM - 1) / BM, E_TASKS);  // (4, 32, 16)
    gemm1_kernel<<<grid, NTHREADS>>>(x, W1, b1);

    layer2_kernel<<<N_SAMPLES / 8, 256>>>(keys, W2, b2, out);

    l1_kernel<<<E_TASKS, 256>>>(W1, b1, W2, b2);
    final_kernel<<<1, 32>>>(out, out_size);
}

// round 2
// speedup vs baseline: 1.1862x; 1.1862x over previous
#include <cuda_runtime.h>

// Problem constants (fixed by the reference)
#define N_SAMPLES 4096
#define D_IN      1024
#define B_MID     512
#define E_TASKS   16
#define L1_LAMBDA 1e-4f
#define L1_SLICES 32

// GEMM tiling
#define BM 128
#define BN 128
#define BK 16
#define TM 8
#define TN 8
#define NTHREADS 256

// Static device scratch (no allocations allowed)
__device__ float g_h[(size_t)N_SAMPLES * B_MID];   // relu(h) staging, 8 MB
__device__ int   g_perm[N_SAMPLES];                // sample indices grouped by expert
__device__ int   g_counts[E_TASKS];
__device__ int   g_offsets[E_TASKS];
__device__ float g_l1part[E_TASKS * L1_SLICES];

// ---------------------------------------------------------------------------
// Kernel 1: group samples by expert (single block).
// ---------------------------------------------------------------------------
__global__ void sort_kernel(const int* __restrict__ keys) {
    __shared__ int cnt[E_TASKS];
    __shared__ int off[E_TASKS];
    __shared__ int cur[E_TASKS];
    int tid = threadIdx.x;
    if (tid < E_TASKS) { cnt[tid] = 0; cur[tid] = 0; }
    __syncthreads();
    for (int n = tid; n < N_SAMPLES; n += blockDim.x)
        atomicAdd(&cnt[keys[n]], 1);
    __syncthreads();
    if (tid == 0) {
        int s = 0;
        for (int e = 0; e < E_TASKS; e++) { off[e] = s; s += cnt[e]; }
    }
    __syncthreads();
    if (tid < E_TASKS) { g_counts[tid] = cnt[tid]; g_offsets[tid] = off[tid]; }
    for (int n = tid; n < N_SAMPLES; n += blockDim.x) {
        int e = keys[n];
        int p = atomicAdd(&cur[e], 1);
        g_perm[off[e] + p] = n;
    }
}

// ---------------------------------------------------------------------------
// Packed fp32x2 FMA helpers (sm_103a FFMA2 — only reachable via PTX)
// ---------------------------------------------------------------------------
__device__ __forceinline__ unsigned long long dup_f32x2(float a) {
    unsigned long long r;
    asm("mov.b64 %0, {%1, %1};" : "=l"(r) : "f"(a));
    return r;
}
__device__ __forceinline__ void fma_f32x2(unsigned long long& d,
                                          unsigned long long a,
                                          unsigned long long b) {
    asm("fma.rn.f32x2 %0, %1, %2, %0;" : "+l"(d) : "l"(a), "l"(b));
}
__device__ __forceinline__ void unpack_f32x2(unsigned long long v,
                                             float& lo, float& hi) {
    asm("mov.b64 {%0, %1}, %2;" : "=f"(lo), "=f"(hi) : "l"(v));
}

// ---------------------------------------------------------------------------
// Kernel 2: per-expert gathered SGEMM  h = relu(Xg @ W1[e]^T + b1[e])
// NT gemm, tile 128x128x16, 256 threads, 8x8 micro-tiles with the N dimension
// packed into f32x2 pairs (32 FFMA2 per kk per thread).
// ---------------------------------------------------------------------------
__global__ __launch_bounds__(NTHREADS)
void gemm1_kernel(const float* __restrict__ x,
                  const float* __restrict__ W1,
                  const float* __restrict__ b1)
{
    const int e   = blockIdx.z;
    const int cnt = g_counts[e];
    const int m0  = blockIdx.y * BM;
    if (m0 >= cnt) return;
    const int off = g_offsets[e];
    const int n0  = blockIdx.x * BN;

    __shared__ __align__(16) float As[BK][BM];  // [k][m]
    __shared__ __align__(16) float Ws[BK][BN];  // [k][b]
    __shared__ int rows[BM];

    const int tid = threadIdx.x;
    const int tx  = tid & 15;    // 0..15 -> b groups
    const int ty  = tid >> 4;    // 0..15 -> m groups

    if (tid < BM) {
        int m = m0 + tid;
        rows[tid] = (m < cnt) ? g_perm[off + m] : -1;
    }
    __syncthreads();

    unsigned long long acc2[TM][TN / 2];
#pragma unroll
    for (int i = 0; i < TM; i++)
#pragma unroll
        for (int j = 0; j < TN / 2; j++) acc2[i][j] = 0ull;

    const float* W1e = W1 + ((size_t)e * B_MID + n0) * D_IN;

    for (int k0 = 0; k0 < D_IN; k0 += BK) {
        // Load A tile: 128 rows x 16 k = 512 float4, 2 per thread.
#pragma unroll
        for (int t = 0; t < 2; t++) {
            int f = tid + t * NTHREADS;
            int m = f >> 2;
            int c = f & 3;
            int r = rows[m];
            float4 v = make_float4(0.f, 0.f, 0.f, 0.f);
            if (r >= 0) v = *(const float4*)(x + (size_t)r * D_IN + k0 + 4 * c);
            As[4 * c + 0][m] = v.x;
            As[4 * c + 1][m] = v.y;
            As[4 * c + 2][m] = v.z;
            As[4 * c + 3][m] = v.w;
        }
        // Load W tile (rows are contiguous b-rows of W1[e])
#pragma unroll
        for (int t = 0; t < 2; t++) {
            int f = tid + t * NTHREADS;
            int b = f >> 2;
            int c = f & 3;
            float4 v = *(const float4*)(W1e + (size_t)b * D_IN + k0 + 4 * c);
            Ws[4 * c + 0][b] = v.x;
            Ws[4 * c + 1][b] = v.y;
            Ws[4 * c + 2][b] = v.z;
            Ws[4 * c + 3][b] = v.w;
        }
        __syncthreads();

#pragma unroll
        for (int kk = 0; kk < BK; kk++) {
            float a[TM];
            *(float4*)&a[0] = *(const float4*)&As[kk][ty * TM + 0];
            *(float4*)&a[4] = *(const float4*)&As[kk][ty * TM + 4];
            // w pairs: 8 contiguous floats -> 4 packed f32x2
            unsigned long long w2[TN / 2];
            {
                const ulonglong2* wp = (const ulonglong2*)&Ws[kk][tx * TN];
                ulonglong2 wA = wp[0];
                ulonglong2 wB = wp[1];
                w2[0] = wA.x; w2[1] = wA.y; w2[2] = wB.x; w2[3] = wB.y;
            }
#pragma unroll
            for (int i = 0; i < TM; i++) {
                unsigned long long ad = dup_f32x2(a[i]);
#pragma unroll
                for (int j = 0; j < TN / 2; j++)
                    fma_f32x2(acc2[i][j], ad, w2[j]);
            }
        }
        __syncthreads();
    }

    // Epilogue: h = relu(acc + b1[e][b]) -> g_h[row][b]
    float bb[TN];
#pragma unroll
    for (int j = 0; j < TN; j++)
        bb[j] = b1[e * B_MID + n0 + tx * TN + j];

#pragma unroll
    for (int i = 0; i < TM; i++) {
        int mi = ty * TM + i;
        if (m0 + mi < cnt) {
            int r = rows[mi];
            float* hp = g_h + (size_t)r * B_MID + n0 + tx * TN;
            float av[TN];
#pragma unroll
            for (int j = 0; j < TN / 2; j++)
                unpack_f32x2(acc2[i][j], av[2 * j], av[2 * j + 1]);
            float4 v0, v1;
            v0.x = fmaxf(av[0] + bb[0], 0.f);
            v0.y = fmaxf(av[1] + bb[1], 0.f);
            v0.z = fmaxf(av[2] + bb[2], 0.f);
            v0.w = fmaxf(av[3] + bb[3], 0.f);
            v1.x = fmaxf(av[4] + bb[4], 0.f);
            v1.y = fmaxf(av[5] + bb[5], 0.f);
            v1.z = fmaxf(av[6] + bb[6], 0.f);
            v1.w = fmaxf(av[7] + bb[7], 0.f);
            *(float4*)(hp + 0) = v0;
            *(float4*)(hp + 4) = v1;
        }
    }
}

// ---------------------------------------------------------------------------
// Kernel 3: layer 2 — one warp per sample. out[n] = h[n] . W2[e] + b2[e]
// ---------------------------------------------------------------------------
__global__ void layer2_kernel(const int* __restrict__ keys,
                              const float* __restrict__ W2,
                              const float* __restrict__ b2,
                              float* __restrict__ out)
{
    int gwarp = (blockIdx.x * blockDim.x + threadIdx.x) >> 5;
    int lane  = threadIdx.x & 31;
    if (gwarp >= N_SAMPLES) return;
    int e = keys[gwarp];
    const float* h = g_h + (size_t)gwarp * B_MID;
    const float* w = W2 + (size_t)e * B_MID;
    float s = 0.f;
#pragma unroll
    for (int b = lane; b < B_MID; b += 32)
        s = fmaf(h[b], w[b], s);
#pragma unroll
    for (int o = 16; o > 0; o >>= 1)
        s += __shfl_xor_sync(0xffffffffu, s, o);
    if (lane == 0) out[gwarp] = s + b2[e];
}

// ---------------------------------------------------------------------------
// Kernel 4: per-expert L1 partials. Grid (E_TASKS, L1_SLICES) = 512 blocks.
// Each block reduces a fixed slice of expert e's params (deterministic).
// ---------------------------------------------------------------------------
__global__ void l1_kernel(const float* __restrict__ W1,
                          const float* __restrict__ b1,
                          const float* __restrict__ W2,
                          const float* __restrict__ b2)
{
    const int e     = blockIdx.x;
    const int slice = blockIdx.y;
    const int tid   = threadIdx.x;  // 256 threads
    const int W1_PER = B_MID * D_IN;           // 524288 elems
    const int SLICE_ELEMS = W1_PER / L1_SLICES; // 16384 (multiple of 4*256)

    float s = 0.f;
    const float4* w1 = (const float4*)(W1 + (size_t)e * W1_PER + (size_t)slice * SLICE_ELEMS);
    for (int i = tid; i < SLICE_ELEMS / 4; i += 256) {
        float4 v = w1[i];
        s += fabsf(v.x) + fabsf(v.y) + fabsf(v.z) + fabsf(v.w);
    }
    if (slice == 0) {
        const float* bb1 = b1 + e * B_MID;
        for (int i = tid; i < B_MID; i += 256) s += fabsf(bb1[i]);
        const float* w2 = W2 + e * B_MID;
        for (int i = tid; i < B_MID; i += 256) s += fabsf(w2[i]);
        if (tid == 0) s += fabsf(b2[e]);
    }

    __shared__ float red[256];
    red[tid] = s;
    __syncthreads();
    for (int st = 128; st > 0; st >>= 1) {
        if (tid < st) red[tid] += red[tid + st];
        __syncthreads();
    }
    if (tid == 0) g_l1part[e * L1_SLICES + slice] = red[0];
}

// ---------------------------------------------------------------------------
// Kernel 5: final L1 scalar -> out[N] (only if the output buffer carries it)
// Deterministic: fixed-order reduction per expert, fixed-order expert sum.
// ---------------------------------------------------------------------------
__global__ void final_kernel(float* __restrict__ out, int out_size) {
    if (threadIdx.x == 0 && blockIdx.x == 0 && out_size > N_SAMPLES) {
        float s = 0.f;
        for (int e = 0; e < E_TASKS; e++) {
            float pe = 0.f;
            for (int j = 0; j < L1_SLICES; j++)
                pe += g_l1part[e * L1_SLICES + j];
            s += (float)g_counts[e] * pe;
        }
        out[N_SAMPLES] = L1_LAMBDA * s;
    }
}

// ---------------------------------------------------------------------------
extern "C" void kernel_launch(void* const* d_in, const int* in_sizes, int n_in,
                              void* d_out, int out_size)
{
    const float* x    = (const float*)d_in[0];
    const int*   keys = (const int*)  d_in[1];
    const float* W1   = (const float*)d_in[2];
    const float* b1   = (const float*)d_in[3];
    const float* W2   = (const float*)d_in[4];
    const float* b2   = (const float*)d_in[5];
    float* out = (float*)d_out;

    sort_kernel<<<1, 256>>>(keys);

    dim3 grid(B_MID / BN, (N_SAMPLES + BM - 1) / BM, E_TASKS);  // (4, 32, 16)
    gemm1_kernel<<<grid, NTHREADS>>>(x, W1, b1);

    layer2_kernel<<<N_SAMPLES / 8, 256>>>(keys, W2, b2, out);

    dim3 l1grid(E_TASKS, L1_SLICES);
    l1_kernel<<<l1grid, 256>>>(W1, b1, W2, b2);
    final_kernel<<<1, 32>>>(out, out_size);
}

// round 3
// speedup vs baseline: 2.2177x; 1.8697x over previous
#include <cuda_runtime.h>
#include <cuda_bf16.h>
#include <cstdint>

// Problem constants (fixed by the reference)
#define N_SAMPLES 4096
#define D_IN      1024
#define B_MID     512
#define E_TASKS   16
#define L1_LAMBDA 1e-4f
#define L1_SLICES 64

// GEMM tiling
#define BM 128
#define BN 128
#define BK 32
#define NTHREADS 256

// Static device scratch (no allocations allowed)
__device__ __nv_bfloat16 g_xhi[(size_t)N_SAMPLES * D_IN];
__device__ __nv_bfloat16 g_xlo[(size_t)N_SAMPLES * D_IN];
__device__ __nv_bfloat16 g_whi[(size_t)E_TASKS * B_MID * D_IN];
__device__ __nv_bfloat16 g_wlo[(size_t)E_TASKS * B_MID * D_IN];
__device__ float g_h[(size_t)N_SAMPLES * B_MID];
__device__ int   g_perm[N_SAMPLES];
__device__ int   g_counts[E_TASKS];
__device__ int   g_offsets[E_TASKS];
__device__ float g_l1part[E_TASKS * L1_SLICES];

// ---------------------------------------------------------------------------
// Kernel 0: split fp32 -> bf16 hi/lo (hi = rn(f), lo = rn(f - hi))
// ---------------------------------------------------------------------------
__global__ void split_kernel(const float* __restrict__ src,
                             __nv_bfloat16* __restrict__ hi,
                             __nv_bfloat16* __restrict__ lo, int n4)
{
    int i = blockIdx.x * blockDim.x + threadIdx.x;
    if (i >= n4) return;
    float4 v = ((const float4*)src)[i];
    __nv_bfloat16 h0 = __float2bfloat16_rn(v.x);
    __nv_bfloat16 h1 = __float2bfloat16_rn(v.y);
    __nv_bfloat16 h2 = __float2bfloat16_rn(v.z);
    __nv_bfloat16 h3 = __float2bfloat16_rn(v.w);
    __nv_bfloat16 l0 = __float2bfloat16_rn(v.x - __bfloat162float(h0));
    __nv_bfloat16 l1 = __float2bfloat16_rn(v.y - __bfloat162float(h1));
    __nv_bfloat16 l2 = __float2bfloat16_rn(v.z - __bfloat162float(h2));
    __nv_bfloat16 l3 = __float2bfloat16_rn(v.w - __bfloat162float(h3));
    ((__nv_bfloat162*)hi)[2 * i + 0] = __nv_bfloat162(h0, h1);
    ((__nv_bfloat162*)hi)[2 * i + 1] = __nv_bfloat162(h2, h3);
    ((__nv_bfloat162*)lo)[2 * i + 0] = __nv_bfloat162(l0, l1);
    ((__nv_bfloat162*)lo)[2 * i + 1] = __nv_bfloat162(l2, l3);
}

// ---------------------------------------------------------------------------
// Kernel 1: group samples by expert (single block).
// ---------------------------------------------------------------------------
__global__ void sort_kernel(const int* __restrict__ keys) {
    __shared__ int cnt[E_TASKS];
    __shared__ int off[E_TASKS];
    __shared__ int cur[E_TASKS];
    int tid = threadIdx.x;
    if (tid < E_TASKS) { cnt[tid] = 0; cur[tid] = 0; }
    __syncthreads();
    for (int n = tid; n < N_SAMPLES; n += blockDim.x)
        atomicAdd(&cnt[keys[n]], 1);
    __syncthreads();
    if (tid == 0) {
        int s = 0;
        for (int e = 0; e < E_TASKS; e++) { off[e] = s; s += cnt[e]; }
    }
    __syncthreads();
    if (tid < E_TASKS) { g_counts[tid] = cnt[tid]; g_offsets[tid] = off[tid]; }
    for (int n = tid; n < N_SAMPLES; n += blockDim.x) {
        int e = keys[n];
        int p = atomicAdd(&cur[e], 1);
        g_perm[off[e] + p] = n;
    }
}

// ---------------------------------------------------------------------------
// Tensor-core helpers
// ---------------------------------------------------------------------------
__device__ __forceinline__ uint32_t smem_u32(const void* p) {
    return (uint32_t)__cvta_generic_to_shared(p);
}
__device__ __forceinline__ void ldsm_x4(uint32_t& r0, uint32_t& r1,
                                        uint32_t& r2, uint32_t& r3, uint32_t a) {
    asm volatile("ldmatrix.sync.aligned.m8n8.x4.shared.b16 {%0,%1,%2,%3}, [%4];"
                 : "=r"(r0), "=r"(r1), "=r"(r2), "=r"(r3) : "r"(a));
}
__device__ __forceinline__ void ldsm_x2(uint32_t& r0, uint32_t& r1, uint32_t a) {
    asm volatile("ldmatrix.sync.aligned.m8n8.x2.shared.b16 {%0,%1}, [%2];"
                 : "=r"(r0), "=r"(r1) : "r"(a));
}
__device__ __forceinline__ void mma_bf16(float (&d)[4], const uint32_t (&a)[4],
                                         const uint32_t (&b)[2]) {
    asm volatile("mma.sync.aligned.m16n8k16.row.col.f32.bf16.bf16.f32 "
                 "{%0,%1,%2,%3}, {%4,%5,%6,%7}, {%8,%9}, {%0,%1,%2,%3};"
                 : "+f"(d[0]), "+f"(d[1]), "+f"(d[2]), "+f"(d[3])
                 : "r"(a[0]), "r"(a[1]), "r"(a[2]), "r"(a[3]),
                   "r"(b[0]), "r"(b[1]));
}
// 16B-chunk XOR swizzle: rows stride 64B (4 chunks); conflict-free for
// 8-consecutive-row ldmatrix access.
__device__ __forceinline__ int swc(int row, int c) { return c ^ ((row >> 1) & 3); }

// ---------------------------------------------------------------------------
// Kernel 2: grouped bf16x3 GEMM  h = relu(Xg @ W1[e]^T + b1[e])
// Block tile 128x128x32, 8 warps (2m x 4n), warp tile 64x32.
// ---------------------------------------------------------------------------
__global__ __launch_bounds__(NTHREADS, 1)
void gemm1_kernel(const float* __restrict__ b1)
{
    const int e   = blockIdx.z;
    const int cnt = g_counts[e];
    const int m0  = blockIdx.y * BM;
    if (m0 >= cnt) return;
    const int off = g_offsets[e];
    const int n0  = blockIdx.x * BN;

    __shared__ __align__(16) uint4 sAh[BM * 4];
    __shared__ __align__(16) uint4 sAl[BM * 4];
    __shared__ __align__(16) uint4 sBh[BM * 4];
    __shared__ __align__(16) uint4 sBl[BM * 4];
    __shared__ int rows[BM];

    const int tid  = threadIdx.x;
    const int lane = tid & 31;
    const int warp = tid >> 5;
    const int wm   = warp >> 2;  // 0..1
    const int wn   = warp & 3;   // 0..3

    if (tid < BM) {
        int m = m0 + tid;
        rows[tid] = (m < cnt) ? g_perm[off + m] : -1;
    }
    __syncthreads();

    // Per-thread fixed load slots: t in {0,1}: flat = tid + 256t
    const int cA   = tid & 3;                 // 16B chunk within row
    const int rI0  = tid >> 2;                // tile row for t=0
    const int rI1  = (tid + 256) >> 2;        // tile row for t=1
    const int rA0  = rows[rI0];
    const int rA1  = rows[rI1];
    const int sIdx0 = rI0 * 4 + swc(rI0, cA);
    const int sIdx1 = rI1 * 4 + swc(rI1, cA);

    const __nv_bfloat16* pA0h = g_xhi + (size_t)(rA0 < 0 ? 0 : rA0) * D_IN + cA * 8;
    const __nv_bfloat16* pA0l = g_xlo + (size_t)(rA0 < 0 ? 0 : rA0) * D_IN + cA * 8;
    const __nv_bfloat16* pA1h = g_xhi + (size_t)(rA1 < 0 ? 0 : rA1) * D_IN + cA * 8;
    const __nv_bfloat16* pA1l = g_xlo + (size_t)(rA1 < 0 ? 0 : rA1) * D_IN + cA * 8;
    const size_t wb0 = (size_t)(e * B_MID + n0 + rI0) * D_IN + cA * 8;
    const size_t wb1 = (size_t)(e * B_MID + n0 + rI1) * D_IN + cA * 8;
    const __nv_bfloat16* pB0h = g_whi + wb0;
    const __nv_bfloat16* pB0l = g_wlo + wb0;
    const __nv_bfloat16* pB1h = g_whi + wb1;
    const __nv_bfloat16* pB1l = g_wlo + wb1;

    float acc[4][4][4];
#pragma unroll
    for (int i = 0; i < 4; i++)
#pragma unroll
        for (int j = 0; j < 4; j++)
#pragma unroll
            for (int q = 0; q < 4; q++) acc[i][j][q] = 0.f;

    const uint4 z4 = make_uint4(0, 0, 0, 0);
    uint4 lv[8];

    // Prologue: load k0 = 0 and stage it
    {
        lv[0] = (rA0 >= 0) ? *(const uint4*)(pA0h) : z4;
        lv[1] = (rA1 >= 0) ? *(const uint4*)(pA1h) : z4;
        lv[2] = (rA0 >= 0) ? *(const uint4*)(pA0l) : z4;
        lv[3] = (rA1 >= 0) ? *(const uint4*)(pA1l) : z4;
        lv[4] = *(const uint4*)(pB0h);
        lv[5] = *(const uint4*)(pB1h);
        lv[6] = *(const uint4*)(pB0l);
        lv[7] = *(const uint4*)(pB1l);
        sAh[sIdx0] = lv[0]; sAh[sIdx1] = lv[1];
        sAl[sIdx0] = lv[2]; sAl[sIdx1] = lv[3];
        sBh[sIdx0] = lv[4]; sBh[sIdx1] = lv[5];
        sBl[sIdx0] = lv[6]; sBl[sIdx1] = lv[7];
    }
    __syncthreads();

    const uint32_t baseAh = smem_u32(sAh);
    const uint32_t baseAl = smem_u32(sAl);
    const uint32_t baseBh = smem_u32(sBh);
    const uint32_t baseBl = smem_u32(sBl);

    for (int k0 = 0; ; ) {
        const int kn = k0 + BK;
        const bool has_next = (kn < D_IN);
        if (has_next) {
            lv[0] = (rA0 >= 0) ? *(const uint4*)(pA0h + kn) : z4;
            lv[1] = (rA1 >= 0) ? *(const uint4*)(pA1h + kn) : z4;
            lv[2] = (rA0 >= 0) ? *(const uint4*)(pA0l + kn) : z4;
            lv[3] = (rA1 >= 0) ? *(const uint4*)(pA1l + kn) : z4;
            lv[4] = *(const uint4*)(pB0h + kn);
            lv[5] = *(const uint4*)(pB1h + kn);
            lv[6] = *(const uint4*)(pB0l + kn);
            lv[7] = *(const uint4*)(pB1l + kn);
        }

        // Compute two k16 steps from staged smem
#pragma unroll
        for (int t = 0; t < 2; t++) {
            // B fragments (4 n-tiles)
            uint32_t bh[4][2], bl[4][2];
#pragma unroll
            for (int j = 0; j < 4; j++) {
                int brow = wn * 32 + j * 8 + (lane & 7);
                int bc   = 2 * t + ((lane >> 3) & 1);
                uint32_t o = (uint32_t)(brow * 4 + swc(brow, bc)) * 16u;
                ldsm_x2(bh[j][0], bh[j][1], baseBh + o);
                ldsm_x2(bl[j][0], bl[j][1], baseBl + o);
            }
            // A fragments (4 m-tiles) + MMAs
#pragma unroll
            for (int i = 0; i < 4; i++) {
                int arow = wm * 64 + i * 16 + (lane & 15);
                int ac   = 2 * t + (lane >> 4);
                uint32_t o = (uint32_t)(arow * 4 + swc(arow, ac)) * 16u;
                uint32_t ah[4], al[4];
                ldsm_x4(ah[0], ah[1], ah[2], ah[3], baseAh + o);
                ldsm_x4(al[0], al[1], al[2], al[3], baseAl + o);
#pragma unroll
                for (int j = 0; j < 4; j++) {
                    mma_bf16(acc[i][j], ah, bh[j]);
                    mma_bf16(acc[i][j], ah, bl[j]);
                    mma_bf16(acc[i][j], al, bh[j]);
                }
            }
        }

        if (!has_next) break;
        __syncthreads();
        sAh[sIdx0] = lv[0]; sAh[sIdx1] = lv[1];
        sAl[sIdx0] = lv[2]; sAl[sIdx1] = lv[3];
        sBh[sIdx0] = lv[4]; sBh[sIdx1] = lv[5];
        sBl[sIdx0] = lv[6]; sBl[sIdx1] = lv[7];
        __syncthreads();
        k0 = kn;
    }

    // Epilogue: relu(acc + b1) -> g_h (gathered rows)
    const int g  = lane >> 2;
    const int cq = lane & 3;
#pragma unroll
    for (int j = 0; j < 4; j++) {
        int gcol = n0 + wn * 32 + j * 8 + 2 * cq;
        float2 bb = *(const float2*)(b1 + e * B_MID + gcol);
#pragma unroll
        for (int i = 0; i < 4; i++) {
            int mi0 = wm * 64 + i * 16 + g;
            int mi1 = mi0 + 8;
            if (m0 + mi0 < cnt) {
                int r = rows[mi0];
                float2 o;
                o.x = fmaxf(acc[i][j][0] + bb.x, 0.f);
                o.y = fmaxf(acc[i][j][1] + bb.y, 0.f);
                *(float2*)(g_h + (size_t)r * B_MID + gcol) = o;
            }
            if (m0 + mi1 < cnt) {
                int r = rows[mi1];
                float2 o;
                o.x = fmaxf(acc[i][j][2] + bb.x, 0.f);
                o.y = fmaxf(acc[i][j][3] + bb.y, 0.f);
                *(float2*)(g_h + (size_t)r * B_MID + gcol) = o;
            }
        }
    }
}

// ---------------------------------------------------------------------------
// Kernel 3: layer 2 — one warp per sample. out[n] = h[n] . W2[e] + b2[e]
// ---------------------------------------------------------------------------
__global__ void layer2_kernel(const int* __restrict__ keys,
                              const float* __restrict__ W2,
                              const float* __restrict__ b2,
                              float* __restrict__ out)
{
    int gwarp = (blockIdx.x * blockDim.x + threadIdx.x) >> 5;
    int lane  = threadIdx.x & 31;
    if (gwarp >= N_SAMPLES) return;
    int e = keys[gwarp];
    const float4* h = (const float4*)(g_h + (size_t)gwarp * B_MID);
    const float4* w = (const float4*)(W2 + (size_t)e * B_MID);
    float s = 0.f;
#pragma unroll
    for (int b = lane; b < B_MID / 4; b += 32) {
        float4 hv = h[b];
        float4 wv = w[b];
        s = fmaf(hv.x, wv.x, s);
        s = fmaf(hv.y, wv.y, s);
        s = fmaf(hv.z, wv.z, s);
        s = fmaf(hv.w, wv.w, s);
    }
#pragma unroll
    for (int o = 16; o > 0; o >>= 1)
        s += __shfl_xor_sync(0xffffffffu, s, o);
    if (lane == 0) out[gwarp] = s + b2[e];
}

// ---------------------------------------------------------------------------
// Kernel 4: per-expert L1 partials (deterministic fixed-order slices)
// ---------------------------------------------------------------------------
__global__ void l1_kernel(const float* __restrict__ W1,
                          const float* __restrict__ b1,
                          const float* __restrict__ W2,
                          const float* __restrict__ b2)
{
    const int e     = blockIdx.x;
    const int slice = blockIdx.y;
    const int tid   = threadIdx.x;  // 256 threads
    const int W1_PER = B_MID * D_IN;                 // 524288
    const int SLICE_ELEMS = W1_PER / L1_SLICES;      // 8192

    float s = 0.f;
    const float4* w1 = (const float4*)(W1 + (size_t)e * W1_PER + (size_t)slice * SLICE_ELEMS);
#pragma unroll
    for (int i = tid; i < SLICE_ELEMS / 4; i += 256) {
        float4 v = w1[i];
        s += fabsf(v.x) + fabsf(v.y) + fabsf(v.z) + fabsf(v.w);
    }
    if (slice == 0) {
        const float* bb1 = b1 + e * B_MID;
        for (int i = tid; i < B_MID; i += 256) s += fabsf(bb1[i]);
        const float* w2 = W2 + e * B_MID;
        for (int i = tid; i < B_MID; i += 256) s += fabsf(w2[i]);
        if (tid == 0) s += fabsf(b2[e]);
    }

    __shared__ float red[256];
    red[tid] = s;
    __syncthreads();
    for (int st = 128; st > 0; st >>= 1) {
        if (tid < st) red[tid] += red[tid + st];
        __syncthreads();
    }
    if (tid == 0) g_l1part[e * L1_SLICES + slice] = red[0];
}

// ---------------------------------------------------------------------------
// Kernel 5: final L1 scalar -> out[N]
// ---------------------------------------------------------------------------
__global__ void final_kernel(float* __restrict__ out, int out_size) {
    if (threadIdx.x == 0 && blockIdx.x == 0 && out_size > N_SAMPLES) {
        float s = 0.f;
        for (int e = 0; e < E_TASKS; e++) {
            float pe = 0.f;
            for (int j = 0; j < L1_SLICES; j++)
                pe += g_l1part[e * L1_SLICES + j];
            s += (float)g_counts[e] * pe;
        }
        out[N_SAMPLES] = L1_LAMBDA * s;
    }
}

// ---------------------------------------------------------------------------
extern "C" void kernel_launch(void* const* d_in, const int* in_sizes, int n_in,
                              void* d_out, int out_size)
{
    const float* x    = (const float*)d_in[0];
    const int*   keys = (const int*)  d_in[1];
    const float* W1   = (const float*)d_in[2];
    const float* b1   = (const float*)d_in[3];
    const float* W2   = (const float*)d_in[4];
    const float* b2   = (const float*)d_in[5];
    float* out = (float*)d_out;

    __nv_bfloat16 *xhi, *xlo, *whi, *wlo;
    cudaGetSymbolAddress((void**)&xhi, g_xhi);
    cudaGetSymbolAddress((void**)&xlo, g_xlo);
    cudaGetSymbolAddress((void**)&whi, g_whi);
    cudaGetSymbolAddress((void**)&wlo, g_wlo);

    split_kernel<<<(N_SAMPLES * D_IN / 4 + 255) / 256, 256>>>(x, xhi, xlo, N_SAMPLES * D_IN / 4);
    split_kernel<<<(E_TASKS * B_MID * D_IN / 4 + 255) / 256, 256>>>(W1, whi, wlo, E_TASKS * B_MID * D_IN / 4);

    sort_kernel<<<1, 256>>>(keys);

    dim3 grid(B_MID / BN, (N_SAMPLES + BM - 1) / BM, E_TASKS);  // (4, 32, 16)
    gemm1_kernel<<<grid, NTHREADS>>>(b1);

    layer2_kernel<<<N_SAMPLES / 8, 256>>>(keys, W2, b2, out);

    dim3 l1grid(E_TASKS, L1_SLICES);
    l1_kernel<<<l1grid, 256>>>(W1, b1, W2, b2);
    final_kernel<<<1, 32>>>(out, out_size);
}

// round 5
// speedup vs baseline: 3.0889x; 1.3928x over previous
#include <cuda_runtime.h>
#include <cuda_bf16.h>
#include <cstdint>

// Problem constants (fixed by the reference)
#define N_SAMPLES 4096
#define D_IN      1024
#define B_MID     512
#define E_TASKS   16
#define L1_LAMBDA 1e-4f
#define L1_SLICES 32   // W1 slices per expert (512 blocks total in split_w)

// GEMM tiling
#define BM 64
#define BN 128
#define BK 32
#define NTHREADS 256
#define NITER (D_IN / BK)   // 32
#define NSTAGE 3

// Dynamic smem layout (uint4 units):
//   sAh: [0, 768)      3 stages x 256 (64 rows x 4 chunks)
//   sAl: [768, 1536)
//   sBh: [1536, 3072)  3 stages x 512 (128 rows x 4 chunks)
//   sBl: [3072, 4608)
//   rows: 64 ints = 16 uint4 at [4608, 4624)
#define SMEM_U4   4624
#define SMEM_BYTES (SMEM_U4 * 16)   // 73984
#define A_STAGE_B 4096   // bytes per A stage
#define B_STAGE_B 8192   // bytes per B stage
#define OFF_AL    (768 * 16)
#define OFF_BH    (1536 * 16)
#define OFF_BL    (3072 * 16)

// Static device scratch (no allocations allowed)
__device__ __nv_bfloat16 g_xhi[(size_t)N_SAMPLES * D_IN];
__device__ __nv_bfloat16 g_xlo[(size_t)N_SAMPLES * D_IN];
__device__ __nv_bfloat16 g_whi[(size_t)E_TASKS * B_MID * D_IN];
__device__ __nv_bfloat16 g_wlo[(size_t)E_TASKS * B_MID * D_IN];
__device__ float g_h[(size_t)N_SAMPLES * B_MID];
__device__ int   g_perm[N_SAMPLES];
__device__ int   g_counts[E_TASKS];
__device__ int   g_offsets[E_TASKS];
__device__ float g_l1part[E_TASKS * L1_SLICES];
__device__ float g_l1small[E_TASKS];

// ---------------------------------------------------------------------------
// Kernel 0a: split x fp32 -> bf16 hi/lo
// ---------------------------------------------------------------------------
__global__ void split_x_kernel(const float* __restrict__ src,
                               __nv_bfloat16* __restrict__ hi,
                               __nv_bfloat16* __restrict__ lo, int n4)
{
    int i = blockIdx.x * blockDim.x + threadIdx.x;
    if (i >= n4) return;
    float4 v = ((const float4*)src)[i];
    __nv_bfloat16 h0 = __float2bfloat16_rn(v.x);
    __nv_bfloat16 h1 = __float2bfloat16_rn(v.y);
    __nv_bfloat16 h2 = __float2bfloat16_rn(v.z);
    __nv_bfloat16 h3 = __float2bfloat16_rn(v.w);
    ((__nv_bfloat162*)hi)[2 * i + 0] = __nv_bfloat162(h0, h1);
    ((__nv_bfloat162*)hi)[2 * i + 1] = __nv_bfloat162(h2, h3);
    ((__nv_bfloat162*)lo)[2 * i + 0] = __nv_bfloat162(
        __float2bfloat16_rn(v.x - __bfloat162float(h0)),
        __float2bfloat16_rn(v.y - __bfloat162float(h1)));
    ((__nv_bfloat162*)lo)[2 * i + 1] = __nv_bfloat162(
        __float2bfloat16_rn(v.z - __bfloat162float(h2)),
        __float2bfloat16_rn(v.w - __bfloat162float(h3)));
}

// ---------------------------------------------------------------------------
// Kernel 0b: split W1 fp32 -> bf16 hi/lo AND accumulate per-slice L1 partials.
// Grid = E_TASKS * L1_SLICES = 512 blocks x 256 threads; each block owns a
// fixed contiguous slice of 4096 float4 (deterministic reduction).
// ---------------------------------------------------------------------------
__global__ void split_w_kernel(const float* __restrict__ W1,
                               __nv_bfloat16* __restrict__ hi,
                               __nv_bfloat16* __restrict__ lo)
{
    const int blk = blockIdx.x;            // 0..511
    const int tid = threadIdx.x;
    const int C4  = (B_MID * D_IN) / L1_SLICES / 4;   // 4096 float4 per slice
    const size_t base = (size_t)blk * C4;
    const float4* src = (const float4*)W1 + base;

    float s = 0.f;
    for (int i = tid; i < C4; i += 256) {
        float4 v = src[i];
        s += fabsf(v.x) + fabsf(v.y) + fabsf(v.z) + fabsf(v.w);
        __nv_bfloat16 h0 = __float2bfloat16_rn(v.x);
        __nv_bfloat16 h1 = __float2bfloat16_rn(v.y);
        __nv_bfloat16 h2 = __float2bfloat16_rn(v.z);
        __nv_bfloat16 h3 = __float2bfloat16_rn(v.w);
        size_t g = base + i;
        ((__nv_bfloat162*)hi)[2 * g + 0] = __nv_bfloat162(h0, h1);
        ((__nv_bfloat162*)hi)[2 * g + 1] = __nv_bfloat162(h2, h3);
        ((__nv_bfloat162*)lo)[2 * g + 0] = __nv_bfloat162(
            __float2bfloat16_rn(v.x - __bfloat162float(h0)),
            __float2bfloat16_rn(v.y - __bfloat162float(h1)));
        ((__nv_bfloat162*)lo)[2 * g + 1] = __nv_bfloat162(
            __float2bfloat16_rn(v.z - __bfloat162float(h2)),
            __float2bfloat16_rn(v.w - __bfloat162float(h3)));
    }

    __shared__ float red[256];
    red[tid] = s;
    __syncthreads();
    for (int st = 128; st > 0; st >>= 1) {
        if (tid < st) red[tid] += red[tid + st];
        __syncthreads();
    }
    if (tid == 0) g_l1part[blk] = red[0];
}

// ---------------------------------------------------------------------------
// Kernel 1: group samples by expert (single block).
// ---------------------------------------------------------------------------
__global__ void sort_kernel(const int* __restrict__ keys) {
    __shared__ int cnt[E_TASKS];
    __shared__ int off[E_TASKS];
    __shared__ int cur[E_TASKS];
    int tid = threadIdx.x;
    if (tid < E_TASKS) { cnt[tid] = 0; cur[tid] = 0; }
    __syncthreads();
    for (int n = tid; n < N_SAMPLES; n += blockDim.x)
        atomicAdd(&cnt[keys[n]], 1);
    __syncthreads();
    if (tid == 0) {
        int s = 0;
        for (int e = 0; e < E_TASKS; e++) { off[e] = s; s += cnt[e]; }
    }
    __syncthreads();
    if (tid < E_TASKS) { g_counts[tid] = cnt[tid]; g_offsets[tid] = off[tid]; }
    for (int n = tid; n < N_SAMPLES; n += blockDim.x) {
        int e = keys[n];
        int p = atomicAdd(&cur[e], 1);
        g_perm[off[e] + p] = n;
    }
}

// ---------------------------------------------------------------------------
// Tensor-core / async-copy helpers
// ---------------------------------------------------------------------------
__device__ __forceinline__ uint32_t smem_u32(const void* p) {
    return (uint32_t)__cvta_generic_to_shared(p);
}
__device__ __forceinline__ void ldsm_x4(uint32_t& r0, uint32_t& r1,
                                        uint32_t& r2, uint32_t& r3, uint32_t a) {
    asm volatile("ldmatrix.sync.aligned.m8n8.x4.shared.b16 {%0,%1,%2,%3}, [%4];"
                 : "=r"(r0), "=r"(r1), "=r"(r2), "=r"(r3) : "r"(a));
}
__device__ __forceinline__ void ldsm_x2(uint32_t& r0, uint32_t& r1, uint32_t a) {
    asm volatile("ldmatrix.sync.aligned.m8n8.x2.shared.b16 {%0,%1}, [%2];"
                 : "=r"(r0), "=r"(r1) : "r"(a));
}
__device__ __forceinline__ void mma_bf16(float (&d)[4], const uint32_t (&a)[4],
                                         const uint32_t (&b)[2]) {
    asm volatile("mma.sync.aligned.m16n8k16.row.col.f32.bf16.bf16.f32 "
                 "{%0,%1,%2,%3}, {%4,%5,%6,%7}, {%8,%9}, {%0,%1,%2,%3};"
                 : "+f"(d[0]), "+f"(d[1]), "+f"(d[2]), "+f"(d[3])
                 : "r"(a[0]), "r"(a[1]), "r"(a[2]), "r"(a[3]),
                   "r"(b[0]), "r"(b[1]));
}
__device__ __forceinline__ void cp16(uint32_t dst, const void* src, bool valid) {
    int sz = valid ? 16 : 0;
    asm volatile("cp.async.cg.shared.global [%0], [%1], 16, %2;"
                 :: "r"(dst), "l"(src), "r"(sz));
}
__device__ __forceinline__ void cp_commit() {
    asm volatile("cp.async.commit_group;");
}
__device__ __forceinline__ void cp_wait1() {
    asm volatile("cp.async.wait_group 1;");
}
// 16B-chunk XOR swizzle: rows stride 64B (4 chunks), conflict-free ldmatrix.
__device__ __forceinline__ int swc(int row, int c) { return c ^ ((row >> 1) & 3); }

// ---------------------------------------------------------------------------
// Kernel 2: grouped bf16x3 GEMM  h = relu(Xg @ W1[e]^T + b1[e])
// Block tile 64x128x32, 8 warps (2m x 4n), warp tile 32x32.
// 3-stage cp.async pipeline, one __syncthreads per K-iter, 2 CTAs/SM.
// ---------------------------------------------------------------------------
__global__ __launch_bounds__(NTHREADS, 2)
void gemm1_kernel(const float* __restrict__ b1)
{
    const int e   = blockIdx.z;
    const int cnt = g_counts[e];
    const int m0  = blockIdx.y * BM;
    if (m0 >= cnt) return;
    const int off = g_offsets[e];
    const int n0  = blockIdx.x * BN;

    extern __shared__ __align__(16) uint4 smem_dyn[];
    int* rows = (int*)(smem_dyn + 4608);

    const int tid  = threadIdx.x;
    const int lane = tid & 31;
    const int warp = tid >> 5;
    const int wm   = warp >> 2;  // 0..1
    const int wn   = warp & 3;   // 0..3

    if (tid < BM) {
        int m = m0 + tid;
        rows[tid] = (m < cnt) ? g_perm[off + m] : -1;
    }
    __syncthreads();

    const uint32_t sbase = smem_u32(smem_dyn);

    // ---- per-thread load slots ----
    const int cA  = tid & 3;          // 16B chunk in row
    const int rI  = tid >> 2;         // 0..63 (A row, B row0)
    const int rB1 = rI + 64;          // B row1
    const uint32_t sAoff  = (uint32_t)(rI  * 4 + swc(rI,  cA)) * 16u;
    const uint32_t sB0off = (uint32_t)(rI  * 4 + swc(rI,  cA)) * 16u;
    const uint32_t sB1off = (uint32_t)(rB1 * 4 + swc(rB1, cA)) * 16u;
    const int  rowA = rows[rI];
    const bool vA   = rowA >= 0;
    const __nv_bfloat16* gAh = g_xhi + (size_t)(vA ? rowA : 0) * D_IN + cA * 8;
    const __nv_bfloat16* gAl = g_xlo + (size_t)(vA ? rowA : 0) * D_IN + cA * 8;
    const size_t w0 = (size_t)(e * B_MID + n0 + rI ) * D_IN + cA * 8;
    const size_t w1 = (size_t)(e * B_MID + n0 + rB1) * D_IN + cA * 8;
    const __nv_bfloat16* gBh0 = g_whi + w0;
    const __nv_bfloat16* gBl0 = g_wlo + w0;
    const __nv_bfloat16* gBh1 = g_whi + w1;
    const __nv_bfloat16* gBl1 = g_wlo + w1;

    // ---- per-warp ldmatrix byte offsets (within a stage) ----
    uint32_t offA[2][2], offB[4][2];
#pragma unroll
    for (int i = 0; i < 2; i++)
#pragma unroll
        for (int t = 0; t < 2; t++) {
            int arow = wm * 32 + i * 16 + (lane & 15);
            int ac   = 2 * t + (lane >> 4);
            offA[i][t] = (uint32_t)(arow * 4 + swc(arow, ac)) * 16u;
        }
#pragma unroll
    for (int j = 0; j < 4; j++)
#pragma unroll
        for (int t = 0; t < 2; t++) {
            int brow = wn * 32 + j * 8 + (lane & 7);
            int bc   = 2 * t + ((lane >> 3) & 1);
            offB[j][t] = (uint32_t)(brow * 4 + swc(brow, bc)) * 16u;
        }

    float acc[2][4][4];
#pragma unroll
    for (int i = 0; i < 2; i++)
#pragma unroll
        for (int j = 0; j < 4; j++)
#pragma unroll
            for (int q = 0; q < 4; q++) acc[i][j][q] = 0.f;

    // ---- issue helper (stage s, element offset k) ----
#define ISSUE(s, k)                                                           \
    do {                                                                      \
        cp16(sbase + (s) * A_STAGE_B + sAoff,           gAh  + (k), vA);      \
        cp16(sbase + OFF_AL + (s) * A_STAGE_B + sAoff,  gAl  + (k), vA);      \
        cp16(sbase + OFF_BH + (s) * B_STAGE_B + sB0off, gBh0 + (k), true);    \
        cp16(sbase + OFF_BH + (s) * B_STAGE_B + sB1off, gBh1 + (k), true);    \
        cp16(sbase + OFF_BL + (s) * B_STAGE_B + sB0off, gBl0 + (k), true);    \
        cp16(sbase + OFF_BL + (s) * B_STAGE_B + sB1off, gBl1 + (k), true);    \
    } while (0)

    // prologue: stages 0, 1
    ISSUE(0, 0);
    cp_commit();
    ISSUE(1, BK);
    cp_commit();

    int stage = 0;
    for (int it = 0; it < NITER; ++it) {
        cp_wait1();          // group(it) complete (group(it+1) may be pending)
        __syncthreads();     // everyone done with compute(it-1) & sees data(it)
        {
            int pf = it + 2;
            if (pf < NITER) {
                int ps = pf - (pf / NSTAGE) * NSTAGE;  // pf % 3
                ISSUE(ps, pf * BK);
            }
            cp_commit();     // always commit (keeps group accounting uniform)
        }

        const uint32_t aH = sbase + stage * A_STAGE_B;
        const uint32_t aL = aH + OFF_AL;
        const uint32_t bH = sbase + OFF_BH + stage * B_STAGE_B;
        const uint32_t bL = bH + (OFF_BL - OFF_BH);

#pragma unroll
        for (int t = 0; t < 2; t++) {
            uint32_t bhf[4][2], blf[4][2];
#pragma unroll
            for (int j = 0; j < 4; j++) {
                ldsm_x2(bhf[j][0], bhf[j][1], bH + offB[j][t]);
                ldsm_x2(blf[j][0], blf[j][1], bL + offB[j][t]);
            }
#pragma unroll
            for (int i = 0; i < 2; i++) {
                uint32_t ah[4], al[4];
                ldsm_x4(ah[0], ah[1], ah[2], ah[3], aH + offA[i][t]);
                ldsm_x4(al[0], al[1], al[2], al[3], aL + offA[i][t]);
#pragma unroll
                for (int j = 0; j < 4; j++) {
                    mma_bf16(acc[i][j], ah, bhf[j]);
                    mma_bf16(acc[i][j], ah, blf[j]);
                    mma_bf16(acc[i][j], al, bhf[j]);
                }
            }
        }
        stage = (stage == NSTAGE - 1) ? 0 : stage + 1;
    }
#undef ISSUE

    // Epilogue: relu(acc + b1) -> g_h (gathered rows)
    const int g  = lane >> 2;
    const int cq = lane & 3;
#pragma unroll
    for (int j = 0; j < 4; j++) {
        int gcol = n0 + wn * 32 + j * 8 + 2 * cq;
        float2 bb = *(const float2*)(b1 + e * B_MID + gcol);
#pragma unroll
        for (int i = 0; i < 2; i++) {
            int mi0 = wm * 32 + i * 16 + g;
            int mi1 = mi0 + 8;
            if (m0 + mi0 < cnt) {
                int r = rows[mi0];
                float2 o;
                o.x = fmaxf(acc[i][j][0] + bb.x, 0.f);
                o.y = fmaxf(acc[i][j][1] + bb.y, 0.f);
                *(float2*)(g_h + (size_t)r * B_MID + gcol) = o;
            }
            if (m0 + mi1 < cnt) {
                int r = rows[mi1];
                float2 o;
                o.x = fmaxf(acc[i][j][2] + bb.x, 0.f);
                o.y = fmaxf(acc[i][j][3] + bb.y, 0.f);
                *(float2*)(g_h + (size_t)r * B_MID + gcol) = o;
            }
        }
    }
}

// ---------------------------------------------------------------------------
// Kernel 3: layer 2 — one warp per sample. out[n] = h[n] . W2[e] + b2[e]
// ---------------------------------------------------------------------------
__global__ void layer2_kernel(const int* __restrict__ keys,
                              const float* __restrict__ W2,
                              const float* __restrict__ b2,
                              float* __restrict__ out)
{
    int gwarp = (blockIdx.x * blockDim.x + threadIdx.x) >> 5;
    int lane  = threadIdx.x & 31;
    if (gwarp >= N_SAMPLES) return;
    int e = keys[gwarp];
    const float4* h = (const float4*)(g_h + (size_t)gwarp * B_MID);
    const float4* w = (const float4*)(W2 + (size_t)e * B_MID);
    float s = 0.f;
#pragma unroll
    for (int b = lane; b < B_MID / 4; b += 32) {
        float4 hv = h[b];
        float4 wv = w[b];
        s = fmaf(hv.x, wv.x, s);
        s = fmaf(hv.y, wv.y, s);
        s = fmaf(hv.z, wv.z, s);
        s = fmaf(hv.w, wv.w, s);
    }
#pragma unroll
    for (int o = 16; o > 0; o >>= 1)
        s += __shfl_xor_sync(0xffffffffu, s, o);
    if (lane == 0) out[gwarp] = s + b2[e];
}

// ---------------------------------------------------------------------------
// Kernel 4: small L1 terms (b1, W2, b2) per expert
// ---------------------------------------------------------------------------
__global__ void l1small_kernel(const float* __restrict__ b1,
                               const float* __restrict__ W2,
                               const float* __restrict__ b2)
{
    const int e   = blockIdx.x;
    const int tid = threadIdx.x;  // 256
    float s = 0.f;
    const float* bb1 = b1 + e * B_MID;
    for (int i = tid; i < B_MID; i += 256) s += fabsf(bb1[i]);
    const float* w2 = W2 + e * B_MID;
    for (int i = tid; i < B_MID; i += 256) s += fabsf(w2[i]);
    if (tid == 0) s += fabsf(b2[e]);

    __shared__ float red[256];
    red[tid] = s;
    __syncthreads();
    for (int st = 128; st > 0; st >>= 1) {
        if (tid < st) red[tid] += red[tid + st];
        __syncthreads();
    }
    if (tid == 0) g_l1small[e] = red[0];
}

// ---------------------------------------------------------------------------
// Kernel 5: final L1 scalar -> out[N] (deterministic fixed-order sums)
// ---------------------------------------------------------------------------
__global__ void final_kernel(float* __restrict__ out, int out_size) {
    if (threadIdx.x == 0 && blockIdx.x == 0 && out_size > N_SAMPLES) {
        float s = 0.f;
        for (int e = 0; e < E_TASKS; e++) {
            float pe = g_l1small[e];
            for (int j = 0; j < L1_SLICES; j++)
                pe += g_l1part[e * L1_SLICES + j];
            s += (float)g_counts[e] * pe;
        }
        out[N_SAMPLES] = L1_LAMBDA * s;
    }
}

// ---------------------------------------------------------------------------
extern "C" void kernel_launch(void* const* d_in, const int* in_sizes, int n_in,
                              void* d_out, int out_size)
{
    const float* x    = (const float*)d_in[0];
    const int*   keys = (const int*)  d_in[1];
    const float* W1   = (const float*)d_in[2];
    const float* b1   = (const float*)d_in[3];
    const float* W2   = (const float*)d_in[4];
    const float* b2   = (const float*)d_in[5];
    float* out = (float*)d_out;

    // Unconditional (no static guards): cheap host-side attribute set.
    cudaFuncSetAttribute(gemm1_kernel,
                         cudaFuncAttributeMaxDynamicSharedMemorySize,
                         SMEM_BYTES);

    __nv_bfloat16 *xhi, *xlo, *whi, *wlo;
    cudaGetSymbolAddress((void**)&xhi, g_xhi);
    cudaGetSymbolAddress((void**)&xlo, g_xlo);
    cudaGetSymbolAddress((void**)&whi, g_whi);
    cudaGetSymbolAddress((void**)&wlo, g_wlo);

    sort_kernel<<<1, 256>>>(keys);
    split_x_kernel<<<(N_SAMPLES * D_IN / 4 + 255) / 256, 256>>>(x, xhi, xlo, N_SAMPLES * D_IN / 4);
    split_w_kernel<<<E_TASKS * L1_SLICES, 256>>>(W1, whi, wlo);

    dim3 grid(B_MID / BN, (N_SAMPLES + BM - 1) / BM, E_TASKS);  // (4, 64, 16)
    gemm1_kernel<<<grid, NTHREADS, SMEM_BYTES>>>(b1);

    layer2_kernel<<<N_SAMPLES / 8, 256>>>(keys, W2, b2, out);

    l1small_kernel<<<E_TASKS, 256>>>(b1, W2, b2);
    final_kernel<<<1, 32>>>(out, out_size);
}

// round 7
// speedup vs baseline: 3.7340x; 1.2088x over previous
#include <cuda_runtime.h>
#include <cuda_bf16.h>
#include <cstdint>

// Problem constants (fixed by the reference)
#define N_SAMPLES 4096
#define D_IN      1024
#define B_MID     512
#define E_TASKS   16
#define L1_LAMBDA 1e-4f
#define L1_SLICES 32

// GEMM tiling: block 64(M) x 128(N) x 64(K), 8 warps (2m x 4n), 2-stage
#define BM 64
#define BN 128
#define BK 64
#define NTHREADS 256
#define NITER (D_IN / BK)   // 16

// Dynamic smem (bytes). Stage = {Ah 8K, Al 8K, Bh 16K, Bl 16K} = 48K.
// Rows are 128B wide (64 bf16), SW128 swizzle chunk' = c ^ (row&7).
#define ST_AL 8192
#define ST_BH 16384
#define ST_BL 32768
#define STAGE_B 49152
#define OFF_ROWS  (2 * STAGE_B)            // 64 ints
#define OFF_PART  (OFF_ROWS + 256)         // 64 x 4 floats
#define SMEM_BYTES (OFF_PART + 1024)       // 99584

// Static device scratch (no allocations allowed)
__device__ __nv_bfloat16 g_xhi[(size_t)N_SAMPLES * D_IN];
__device__ __nv_bfloat16 g_xlo[(size_t)N_SAMPLES * D_IN];
__device__ __nv_bfloat16 g_whi[(size_t)E_TASKS * B_MID * D_IN];
__device__ __nv_bfloat16 g_wlo[(size_t)E_TASKS * B_MID * D_IN];
__device__ float g_part[(size_t)N_SAMPLES * 4];   // layer-2 partials per n-block
__device__ int   g_perm[N_SAMPLES];
__device__ int   g_counts[E_TASKS];
__device__ int   g_offsets[E_TASKS];
__device__ float g_l1part[E_TASKS * L1_SLICES];

// ---------------------------------------------------------------------------
// Kernel 0a: split x fp32 -> bf16 hi/lo
// ---------------------------------------------------------------------------
__global__ void split_x_kernel(const float* __restrict__ src,
                               __nv_bfloat16* __restrict__ hi,
                               __nv_bfloat16* __restrict__ lo, int n4)
{
    int i = blockIdx.x * blockDim.x + threadIdx.x;
    if (i >= n4) return;
    float4 v = ((const float4*)src)[i];
    __nv_bfloat16 h0 = __float2bfloat16_rn(v.x);
    __nv_bfloat16 h1 = __float2bfloat16_rn(v.y);
    __nv_bfloat16 h2 = __float2bfloat16_rn(v.z);
    __nv_bfloat16 h3 = __float2bfloat16_rn(v.w);
    ((__nv_bfloat162*)hi)[2 * i + 0] = __nv_bfloat162(h0, h1);
    ((__nv_bfloat162*)hi)[2 * i + 1] = __nv_bfloat162(h2, h3);
    ((__nv_bfloat162*)lo)[2 * i + 0] = __nv_bfloat162(
        __float2bfloat16_rn(v.x - __bfloat162float(h0)),
        __float2bfloat16_rn(v.y - __bfloat162float(h1)));
    ((__nv_bfloat162*)lo)[2 * i + 1] = __nv_bfloat162(
        __float2bfloat16_rn(v.z - __bfloat162float(h2)),
        __float2bfloat16_rn(v.w - __bfloat162float(h3)));
}

// ---------------------------------------------------------------------------
// Kernel 0b: split W1 fp32 -> bf16 hi/lo AND per-slice L1 partials
// ---------------------------------------------------------------------------
__global__ void split_w_kernel(const float* __restrict__ W1,
                               __nv_bfloat16* __restrict__ hi,
                               __nv_bfloat16* __restrict__ lo)
{
    const int blk = blockIdx.x;            // 0..511
    const int tid = threadIdx.x;
    const int C4  = (B_MID * D_IN) / L1_SLICES / 4;   // 4096 float4 per slice
    const size_t base = (size_t)blk * C4;
    const float4* src = (const float4*)W1 + base;

    float s = 0.f;
    for (int i = tid; i < C4; i += 256) {
        float4 v = src[i];
        s += fabsf(v.x) + fabsf(v.y) + fabsf(v.z) + fabsf(v.w);
        __nv_bfloat16 h0 = __float2bfloat16_rn(v.x);
        __nv_bfloat16 h1 = __float2bfloat16_rn(v.y);
        __nv_bfloat16 h2 = __float2bfloat16_rn(v.z);
        __nv_bfloat16 h3 = __float2bfloat16_rn(v.w);
        size_t g = base + i;
        ((__nv_bfloat162*)hi)[2 * g + 0] = __nv_bfloat162(h0, h1);
        ((__nv_bfloat162*)hi)[2 * g + 1] = __nv_bfloat162(h2, h3);
        ((__nv_bfloat162*)lo)[2 * g + 0] = __nv_bfloat162(
            __float2bfloat16_rn(v.x - __bfloat162float(h0)),
            __float2bfloat16_rn(v.y - __bfloat162float(h1)));
        ((__nv_bfloat162*)lo)[2 * g + 1] = __nv_bfloat162(
            __float2bfloat16_rn(v.z - __bfloat162float(h2)),
            __float2bfloat16_rn(v.w - __bfloat162float(h3)));
    }

    __shared__ float red[256];
    red[tid] = s;
    __syncthreads();
    for (int st = 128; st > 0; st >>= 1) {
        if (tid < st) red[tid] += red[tid + st];
        __syncthreads();
    }
    if (tid == 0) g_l1part[blk] = red[0];
}

// ---------------------------------------------------------------------------
// Kernel 1: group samples by expert (single block).
// ---------------------------------------------------------------------------
__global__ void sort_kernel(const int* __restrict__ keys) {
    __shared__ int cnt[E_TASKS];
    __shared__ int off[E_TASKS];
    __shared__ int cur[E_TASKS];
    int tid = threadIdx.x;
    if (tid < E_TASKS) { cnt[tid] = 0; cur[tid] = 0; }
    __syncthreads();
    for (int n = tid; n < N_SAMPLES; n += blockDim.x)
        atomicAdd(&cnt[keys[n]], 1);
    __syncthreads();
    if (tid == 0) {
        int s = 0;
        for (int e = 0; e < E_TASKS; e++) { off[e] = s; s += cnt[e]; }
    }
    __syncthreads();
    if (tid < E_TASKS) { g_counts[tid] = cnt[tid]; g_offsets[tid] = off[tid]; }
    for (int n = tid; n < N_SAMPLES; n += blockDim.x) {
        int e = keys[n];
        int p = atomicAdd(&cur[e], 1);
        g_perm[off[e] + p] = n;
    }
}

// ---------------------------------------------------------------------------
// Tensor-core / async-copy helpers (legacy mma.sync path — tcgen05 is not
// available through this bench's compile target)
// ---------------------------------------------------------------------------
__device__ __forceinline__ uint32_t smem_u32(const void* p) {
    return (uint32_t)__cvta_generic_to_shared(p);
}
__device__ __forceinline__ void ldsm_x4(uint32_t& r0, uint32_t& r1,
                                        uint32_t& r2, uint32_t& r3, uint32_t a) {
    asm volatile("ldmatrix.sync.aligned.m8n8.x4.shared.b16 {%0,%1,%2,%3}, [%4];"
                 : "=r"(r0), "=r"(r1), "=r"(r2), "=r"(r3) : "r"(a));
}
__device__ __forceinline__ void ldsm_x2(uint32_t& r0, uint32_t& r1, uint32_t a) {
    asm volatile("ldmatrix.sync.aligned.m8n8.x2.shared.b16 {%0,%1}, [%2];"
                 : "=r"(r0), "=r"(r1) : "r"(a));
}
__device__ __forceinline__ void mma_bf16(float (&d)[4], const uint32_t (&a)[4],
                                         const uint32_t (&b)[2]) {
    asm volatile("mma.sync.aligned.m16n8k16.row.col.f32.bf16.bf16.f32 "
                 "{%0,%1,%2,%3}, {%4,%5,%6,%7}, {%8,%9}, {%0,%1,%2,%3};"
                 : "+f"(d[0]), "+f"(d[1]), "+f"(d[2]), "+f"(d[3])
                 : "r"(a[0]), "r"(a[1]), "r"(a[2]), "r"(a[3]),
                   "r"(b[0]), "r"(b[1]));
}
__device__ __forceinline__ void cp16(uint32_t dst, const void* src, bool valid) {
    int sz = valid ? 16 : 0;   // sz=0 -> zero-fill
    asm volatile("cp.async.cg.shared.global [%0], [%1], 16, %2;"
                 :: "r"(dst), "l"(src), "r"(sz));
}
__device__ __forceinline__ void cp_commit() {
    asm volatile("cp.async.commit_group;");
}
__device__ __forceinline__ void cp_wait0() {
    asm volatile("cp.async.wait_group 0;");
}

// ---------------------------------------------------------------------------
// Kernel 2: grouped bf16x3 GEMM + fused layer-2 partial.
// h = relu(Xg @ W1[e]^T + b1[e]); p[n][nblk] = h(128 cols) . W2[e] slice
// ---------------------------------------------------------------------------
__global__ __launch_bounds__(NTHREADS, 2)
void gemm1_kernel(const float* __restrict__ b1, const float* __restrict__ W2)
{
    const int e   = blockIdx.z;
    const int cnt = g_counts[e];
    const int m0  = blockIdx.y * BM;
    if (m0 >= cnt) return;
    const int off = g_offsets[e];
    const int nblk = blockIdx.x;
    const int n0  = nblk * BN;

    extern __shared__ __align__(16) char smem_dyn[];
    int*   rows  = (int*)(smem_dyn + OFF_ROWS);
    float* spart = (float*)(smem_dyn + OFF_PART);   // [64][4]

    const int tid  = threadIdx.x;
    const int lane = tid & 31;
    const int warp = tid >> 5;
    const int wm   = warp >> 2;  // 0..1
    const int wn   = warp & 3;   // 0..3

    if (tid < BM) {
        int m = m0 + tid;
        rows[tid] = (m < cnt) ? g_perm[off + m] : -1;
    }
    __syncthreads();

    const uint32_t sbase = smem_u32(smem_dyn);

    // ---- per-thread cp.async slots: chunk c of 16B, rows r0+32q ----
    const int c  = tid & 7;
    const int r0 = tid >> 3;                         // 0..31
    const uint32_t cpoff = (uint32_t)((c ^ (r0 & 7)) * 16);   // (r&7)==(r0&7)
    // A rows r0, r0+32 ; B rows r0, r0+32, r0+64, r0+96
    uint32_t dstA[2], dstB[4];
    const __nv_bfloat16 *pAh[2], *pAl[2], *pBh[4], *pBl[4];
    bool vA[2];
#pragma unroll
    for (int q = 0; q < 2; q++) {
        int r = r0 + 32 * q;
        dstA[q] = (uint32_t)r * 128u + cpoff;
        int gr = rows[r];
        vA[q] = gr >= 0;
        pAh[q] = g_xhi + (size_t)(vA[q] ? gr : 0) * D_IN + c * 8;
        pAl[q] = g_xlo + (size_t)(vA[q] ? gr : 0) * D_IN + c * 8;
    }
#pragma unroll
    for (int q = 0; q < 4; q++) {
        int r = r0 + 32 * q;
        dstB[q] = (uint32_t)r * 128u + cpoff;
        size_t wb = (size_t)(e * B_MID + n0 + r) * D_IN + c * 8;
        pBh[q] = g_whi + wb;
        pBl[q] = g_wlo + wb;
    }

    // ---- per-warp fragment addressing constants ----
    // A: arow = wm*32 + i*16 + (lane&15); chunk = (2t + (lane>>4)) ^ (arow&7)
    // B: brow = wn*32 + j*8  + (lane&7);  chunk = (2t + ((lane>>3)&1)) ^ (brow&7)
    uint32_t aRowBase[2], aSw[2];
#pragma unroll
    for (int i = 0; i < 2; i++) {
        int arow = wm * 32 + i * 16 + (lane & 15);
        aRowBase[i] = (uint32_t)arow * 128u;
        aSw[i] = (uint32_t)(arow & 7);
    }
    const uint32_t aD = (uint32_t)(lane >> 4);
    uint32_t bRowBase[4], bSw[4];
#pragma unroll
    for (int j = 0; j < 4; j++) {
        int brow = wn * 32 + j * 8 + (lane & 7);
        bRowBase[j] = (uint32_t)brow * 128u;
        bSw[j] = (uint32_t)(brow & 7);
    }
    const uint32_t bD = (uint32_t)((lane >> 3) & 1);

    float acc[2][4][4];
#pragma unroll
    for (int i = 0; i < 2; i++)
#pragma unroll
        for (int j = 0; j < 4; j++)
#pragma unroll
            for (int q = 0; q < 4; q++) acc[i][j][q] = 0.f;

#define TISSUE(s, kbase)                                                      \
    do {                                                                      \
        uint32_t sb_ = sbase + (s) * STAGE_B;                                 \
        _Pragma("unroll")                                                     \
        for (int q = 0; q < 2; q++) {                                         \
            cp16(sb_ + dstA[q],         pAh[q] + (kbase), vA[q]);             \
            cp16(sb_ + ST_AL + dstA[q], pAl[q] + (kbase), vA[q]);             \
        }                                                                     \
        _Pragma("unroll")                                                     \
        for (int q = 0; q < 4; q++) {                                         \
            cp16(sb_ + ST_BH + dstB[q], pBh[q] + (kbase), true);              \
            cp16(sb_ + ST_BL + dstB[q], pBl[q] + (kbase), true);              \
        }                                                                     \
    } while (0)

    TISSUE(0, 0);
    cp_commit();

    for (int it = 0; it < NITER; ++it) {
        const int s = it & 1;
        cp_wait0();          // stage s data landed
        __syncthreads();     // visible to all; prior compute done before issue
        if (it + 1 < NITER) {
            TISSUE(1 - s, (it + 1) * BK);
            cp_commit();
        }

        const uint32_t aH = sbase + s * STAGE_B;
        const uint32_t aL = aH + ST_AL;
        const uint32_t bH = sbase + s * STAGE_B + ST_BH;
        const uint32_t bL = bH + (ST_BL - ST_BH);

#pragma unroll
        for (int t = 0; t < 4; t++) {
            uint32_t bhf[4][2], blf[4][2];
#pragma unroll
            for (int j = 0; j < 4; j++) {
                uint32_t o = bRowBase[j] + ((((2u * t) | bD) ^ bSw[j]) << 4);
                ldsm_x2(bhf[j][0], bhf[j][1], bH + o);
                ldsm_x2(blf[j][0], blf[j][1], bL + o);
            }
#pragma unroll
            for (int i = 0; i < 2; i++) {
                uint32_t o = aRowBase[i] + ((((2u * t) | aD) ^ aSw[i]) << 4);
                uint32_t ah[4], al[4];
                ldsm_x4(ah[0], ah[1], ah[2], ah[3], aH + o);
                ldsm_x4(al[0], al[1], al[2], al[3], aL + o);
#pragma unroll
                for (int j = 0; j < 4; j++) {
                    mma_bf16(acc[i][j], ah, bhf[j]);
                    mma_bf16(acc[i][j], ah, blf[j]);
                    mma_bf16(acc[i][j], al, bhf[j]);
                }
            }
        }
    }
#undef TISSUE

    // ---- fused epilogue: h = relu(acc+b1); partial = h . W2-slice ----
    const int g  = lane >> 2;
    const int cq = lane & 3;
    float p[2][2];   // [i][row-half]
#pragma unroll
    for (int i = 0; i < 2; i++) { p[i][0] = 0.f; p[i][1] = 0.f; }

#pragma unroll
    for (int j = 0; j < 4; j++) {
        int gcol = n0 + wn * 32 + j * 8 + 2 * cq;
        float2 bb = *(const float2*)(b1 + e * B_MID + gcol);
        float2 ww = *(const float2*)(W2 + e * B_MID + gcol);
#pragma unroll
        for (int i = 0; i < 2; i++) {
            float h0 = fmaxf(acc[i][j][0] + bb.x, 0.f);
            float h1 = fmaxf(acc[i][j][1] + bb.y, 0.f);
            float h2 = fmaxf(acc[i][j][2] + bb.x, 0.f);
            float h3 = fmaxf(acc[i][j][3] + bb.y, 0.f);
            p[i][0] = fmaf(h0, ww.x, fmaf(h1, ww.y, p[i][0]));
            p[i][1] = fmaf(h2, ww.x, fmaf(h3, ww.y, p[i][1]));
        }
    }
    // reduce across the 4 lanes of each quad (fixed butterfly order)
#pragma unroll
    for (int i = 0; i < 2; i++)
#pragma unroll
        for (int hh = 0; hh < 2; hh++) {
            p[i][hh] += __shfl_xor_sync(0xffffffffu, p[i][hh], 1);
            p[i][hh] += __shfl_xor_sync(0xffffffffu, p[i][hh], 2);
        }
    if (cq == 0) {
#pragma unroll
        for (int i = 0; i < 2; i++) {
            int row0 = wm * 32 + i * 16 + g;
            spart[row0 * 4 + wn]       = p[i][0];
            spart[(row0 + 8) * 4 + wn] = p[i][1];
        }
    }
    __syncthreads();
    if (tid < BM && (m0 + tid) < cnt) {
        int r = rows[tid];
        float v = spart[tid * 4 + 0] + spart[tid * 4 + 1]
                + spart[tid * 4 + 2] + spart[tid * 4 + 3];
        g_part[(size_t)r * 4 + nblk] = v;
    }
}

// ---------------------------------------------------------------------------
// Kernel 3: finalize. Block 0: L1 scalar. Blocks 1..16: out[n] from partials.
// ---------------------------------------------------------------------------
__global__ void final_kernel(const int* __restrict__ keys,
                             const float* __restrict__ b1,
                             const float* __restrict__ W2,
                             const float* __restrict__ b2,
                             float* __restrict__ out, int out_size)
{
    const int tid = threadIdx.x;
    if (blockIdx.x == 0) {
        if (out_size <= N_SAMPLES) return;
        // 8 warps x 2 experts each: |b1[e]| + |W2[e]| + |b2[e]|
        __shared__ float l1s[E_TASKS];
        int warp = tid >> 5, lane = tid & 31;
#pragma unroll
        for (int k = 0; k < 2; k++) {
            int e = warp * 2 + k;
            float s = 0.f;
            for (int i = lane; i < B_MID; i += 32) {
                s += fabsf(b1[e * B_MID + i]) + fabsf(W2[e * B_MID + i]);
            }
#pragma unroll
            for (int o = 16; o > 0; o >>= 1)
                s += __shfl_xor_sync(0xffffffffu, s, o);
            if (lane == 0) l1s[e] = s + fabsf(b2[e]);
        }
        __syncthreads();
        if (tid == 0) {
            float tot = 0.f;
            for (int e = 0; e < E_TASKS; e++) {
                float pe = l1s[e];
                for (int j = 0; j < L1_SLICES; j++)
                    pe += g_l1part[e * L1_SLICES + j];
                tot += (float)g_counts[e] * pe;
            }
            out[N_SAMPLES] = L1_LAMBDA * tot;
        }
    } else {
        int n = (blockIdx.x - 1) * 256 + tid;
        float4 pv = *(const float4*)(g_part + (size_t)n * 4);
        out[n] = pv.x + pv.y + pv.z + pv.w + b2[keys[n]];
    }
}

// ---------------------------------------------------------------------------
extern "C" void kernel_launch(void* const* d_in, const int* in_sizes, int n_in,
                              void* d_out, int out_size)
{
    const float* x    = (const float*)d_in[0];
    const int*   keys = (const int*)  d_in[1];
    const float* W1   = (const float*)d_in[2];
    const float* b1   = (const float*)d_in[3];
    const float* W2   = (const float*)d_in[4];
    const float* b2   = (const float*)d_in[5];
    float* out = (float*)d_out;

    cudaFuncSetAttribute(gemm1_kernel,
                         cudaFuncAttributeMaxDynamicSharedMemorySize,
                         SMEM_BYTES);

    __nv_bfloat16 *xhi, *xlo, *whi, *wlo;
    cudaGetSymbolAddress((void**)&xhi, g_xhi);
    cudaGetSymbolAddress((void**)&xlo, g_xlo);
    cudaGetSymbolAddress((void**)&whi, g_whi);
    cudaGetSymbolAddress((void**)&wlo, g_wlo);

    sort_kernel<<<1, 256>>>(keys);
    split_x_kernel<<<(N_SAMPLES * D_IN / 4 + 255) / 256, 256>>>(x, xhi, xlo, N_SAMPLES * D_IN / 4);
    split_w_kernel<<<E_TASKS * L1_SLICES, 256>>>(W1, whi, wlo);

    dim3 grid(B_MID / BN, N_SAMPLES / BM, E_TASKS);  // (4, 64, 16)
    gemm1_kernel<<<grid, NTHREADS, SMEM_BYTES>>>(b1, W2);

    final_kernel<<<1 + N_SAMPLES / 256, 256>>>(keys, b1, W2, b2, out, out_size);
}